// round 7
// baseline (speedup 1.0000x reference)
#include <cuda_runtime.h>
#include <math.h>

// NodeConv:
//   xs = [x | gs]  (133)
//   y_neg[n]  = xs[n] @ W_neg[0:133] + b_neg           (per NODE)
//   out[n]    = elu(xs[n] @ W_root + b_root)
//   out[dst] += sum_{e: dst(e)=dst} elu(y_neg[src(e)] + ea[e] @ W_neg[133:139])
//
// Counting-sort by dst -> records int4{src,eid,dst}. Gather processes fixed
// 64-edge windows per warp (perfect balance, MLP=4 everywhere); interior
// dst-runs are exclusively owned (plain RMW), window-boundary runs use
// atomicAdd (~2 per window).

#define NMAX 100000
#define EMAX 1600000
#define NBMAX ((NMAX + 255) / 256)
#define WIN 64

__device__ float g_yneg[(size_t)NMAX * 128];
__device__ int4  g_sed[EMAX];                 // sorted by dst: {src, eid, dst, 0}
__device__ int   g_count[NMAX];
__device__ int   g_offset[NMAX + 1];
__device__ int   g_cursor[NMAX];
__device__ int   g_blocksum[NBMAX];
__device__ int   g_blockoff[NBMAX];
__device__ int   g_is64;

// Branchless ELU: exact for v>=0 (__expf(0)==1), ~1e-7 abs err for v<0.
__device__ __forceinline__ float eluf(float v) {
    float neg = fminf(v, 0.0f);
    float pos = fmaxf(v, 0.0f);
    return pos + (__expf(neg) - 1.0f);
}

__device__ __forceinline__ int load_idx(const void* ei, int is64, size_t pos) {
    return is64 ? (int)__ldg((const long long*)ei + pos)
                : __ldg((const int*)ei + pos);
}

// ---------------------------------------------------------------------------
__global__ void prep_kernel(const int* __restrict__ ei32, int nwords, int N) {
    if (blockIdx.x == 0) {
        int nz = 0;
        for (int i = 1 + 2 * threadIdx.x; i < min(nwords, 4096); i += 2 * blockDim.x)
            nz |= (ei32[i] != 0);
        int any = __syncthreads_or(nz);
        if (threadIdx.x == 0) g_is64 = any ? 0 : 1;
    }
    for (int i = blockIdx.x * blockDim.x + threadIdx.x; i < N;
         i += gridDim.x * blockDim.x)
        g_count[i] = 0;
}

// ---------------------------------------------------------------------------
__global__ void hist_kernel(const void* __restrict__ ei, int E) {
    const int is64 = g_is64;
    int e = blockIdx.x * blockDim.x + threadIdx.x;
    if (e < E) atomicAdd(&g_count[load_idx(ei, is64, e)], 1);
}

// ---------------------------------------------------------------------------
__global__ __launch_bounds__(256)
void scan1_kernel(int N) {
    const int tid = threadIdx.x, lane = tid & 31, w = tid >> 5;
    __shared__ int wsum[8];
    int i = blockIdx.x * 256 + tid;
    int v = (i < N) ? g_count[i] : 0;
#pragma unroll
    for (int o = 16; o > 0; o >>= 1) v += __shfl_down_sync(0xffffffffu, v, o);
    if (lane == 0) wsum[w] = v;
    __syncthreads();
    if (tid == 0) {
        int s = 0;
#pragma unroll
        for (int k = 0; k < 8; k++) s += wsum[k];
        g_blocksum[blockIdx.x] = s;
    }
}

__global__ __launch_bounds__(1024)
void scan2_kernel(int NB) {
    const int tid = threadIdx.x, lane = tid & 31, w = tid >> 5;
    __shared__ int wtot[32];
    int c = (tid < NB) ? g_blocksum[tid] : 0;
    int v = c;
#pragma unroll
    for (int o = 1; o < 32; o <<= 1) {
        int t = __shfl_up_sync(0xffffffffu, v, o);
        if (lane >= o) v += t;
    }
    if (lane == 31) wtot[w] = v;
    __syncthreads();
    if (w == 0) {
        int s = wtot[lane];
#pragma unroll
        for (int o = 1; o < 32; o <<= 1) {
            int t = __shfl_up_sync(0xffffffffu, s, o);
            if (lane >= o) s += t;
        }
        wtot[lane] = s;
    }
    __syncthreads();
    int excl = ((w == 0) ? 0 : wtot[w - 1]) + v - c;
    if (tid < NB) g_blockoff[tid] = excl;
}

__global__ __launch_bounds__(256)
void scan3_kernel(int N, int E) {
    const int tid = threadIdx.x, lane = tid & 31, w = tid >> 5;
    __shared__ int wtot[8];
    int i = blockIdx.x * 256 + tid;
    int c = (i < N) ? g_count[i] : 0;
    int v = c;
#pragma unroll
    for (int o = 1; o < 32; o <<= 1) {
        int t = __shfl_up_sync(0xffffffffu, v, o);
        if (lane >= o) v += t;
    }
    if (lane == 31) wtot[w] = v;
    __syncthreads();
    if (w == 0 && lane < 8) {
        int s = wtot[lane];
#pragma unroll
        for (int o = 1; o < 8; o <<= 1) {
            int t = __shfl_up_sync(0x000000ffu, s, o);
            if (lane >= o) s += t;
        }
        wtot[lane] = s;
    }
    __syncthreads();
    int excl = g_blockoff[blockIdx.x] + ((w == 0) ? 0 : wtot[w - 1]) + v - c;
    if (i < N) {
        g_offset[i] = excl;
        g_cursor[i] = excl;
    }
    if (i == 0) g_offset[N] = E;
}

// ---------------------------------------------------------------------------
// Scatter: write {src, eid, dst} into dst bucket (16B random store).
// ---------------------------------------------------------------------------
__global__ __launch_bounds__(256)
void scatter_kernel(const void* __restrict__ ei, int E) {
    const int is64 = g_is64;
    int e = blockIdx.x * blockDim.x + threadIdx.x;
    if (e >= E) return;
    int dst = load_idx(ei, is64, e);
    int src = load_idx(ei, is64, (size_t)E + e);
    int pos = atomicAdd(&g_cursor[dst], 1);
    g_sed[pos] = make_int4(src, e, dst, 0);
}

// ---------------------------------------------------------------------------
// K1: fused node GEMM. Tile = 64 nodes x 256 outputs (128 y_neg | 128 root).
// ---------------------------------------------------------------------------
__global__ __launch_bounds__(256, 2)
void node_gemm_kernel(const float* __restrict__ x,
                      const float* __restrict__ gs,
                      const float* __restrict__ W_neg,   // [139][128]
                      const float* __restrict__ b_neg,
                      const float* __restrict__ W_root,  // [133][128]
                      const float* __restrict__ b_root,
                      float* __restrict__ out,
                      int N)
{
    __shared__ float As[64][136];
    const int tid = threadIdx.x;
    const int n0 = blockIdx.x * 64;

    for (int i = tid; i < 64 * 133; i += 256) {
        int m = i / 133;
        int k = i - m * 133;
        int n = n0 + m;
        float v = 0.0f;
        if (n < N) v = (k < 128) ? x[(size_t)n * 128 + k]
                                 : gs[(size_t)n * 5 + (k - 128)];
        As[m][k] = v;
    }
    __syncthreads();

    const int c = tid & 31;
    const int r = tid >> 5;
    const bool isRoot = (c >= 16);
    const float* Wsel = isRoot ? W_root : W_neg;
    const float* bsel = isRoot ? b_root : b_neg;
    const int cb = (isRoot ? (c - 16) : c) * 8;

    float acc[8][8];
#pragma unroll
    for (int j = 0; j < 8; j++) {
        float bv = __ldg(bsel + cb + j);
#pragma unroll
        for (int i = 0; i < 8; i++) acc[i][j] = bv;
    }

#pragma unroll 2
    for (int k = 0; k < 133; k++) {
        float4 b0 = __ldg((const float4*)(Wsel + (size_t)k * 128 + cb));
        float4 b1 = __ldg((const float4*)(Wsel + (size_t)k * 128 + cb + 4));
        float a[8];
#pragma unroll
        for (int i = 0; i < 8; i++) a[i] = As[r * 8 + i][k];
#pragma unroll
        for (int i = 0; i < 8; i++) {
            acc[i][0] += a[i] * b0.x;
            acc[i][1] += a[i] * b0.y;
            acc[i][2] += a[i] * b0.z;
            acc[i][3] += a[i] * b0.w;
            acc[i][4] += a[i] * b1.x;
            acc[i][5] += a[i] * b1.y;
            acc[i][6] += a[i] * b1.z;
            acc[i][7] += a[i] * b1.w;
        }
    }

#pragma unroll
    for (int i = 0; i < 8; i++) {
        int n = n0 + r * 8 + i;
        if (n < N) {
            if (isRoot) {
                float4 o0, o1;
                o0.x = eluf(acc[i][0]); o0.y = eluf(acc[i][1]);
                o0.z = eluf(acc[i][2]); o0.w = eluf(acc[i][3]);
                o1.x = eluf(acc[i][4]); o1.y = eluf(acc[i][5]);
                o1.z = eluf(acc[i][6]); o1.w = eluf(acc[i][7]);
                *((float4*)(out + (size_t)n * 128 + cb))     = o0;
                *((float4*)(out + (size_t)n * 128 + cb + 4)) = o1;
            } else {
                *((float4*)(g_yneg + (size_t)n * 128 + cb)) =
                    make_float4(acc[i][0], acc[i][1], acc[i][2], acc[i][3]);
                *((float4*)(g_yneg + (size_t)n * 128 + cb + 4)) =
                    make_float4(acc[i][4], acc[i][5], acc[i][6], acc[i][7]);
            }
        }
    }
}

// ---------------------------------------------------------------------------
// Run flush: interior runs are exclusively owned by this warp -> plain RMW;
// first/last run of a window may be shared with neighbors -> atomicAdd.
// ---------------------------------------------------------------------------
__device__ __forceinline__ void flush_acc(float* __restrict__ out, int dst,
                                          int lane, float4 a, bool atom) {
    float* o = out + (size_t)dst * 128 + lane * 4;
    if (atom) {
        atomicAdd(o + 0, a.x);
        atomicAdd(o + 1, a.y);
        atomicAdd(o + 2, a.z);
        atomicAdd(o + 3, a.w);
    } else {
        float4* p = (float4*)o;
        float4 c = *p;
        c.x += a.x; c.y += a.y; c.z += a.z; c.w += a.w;
        *p = c;
    }
}

// ---------------------------------------------------------------------------
// Gather: one warp per 64-edge window of the dst-sorted record list.
// Unconditional unroll-4 (MLP=4), packed f32x2 FMAs, segmented accumulation.
// ---------------------------------------------------------------------------
__global__ __launch_bounds__(256)
void gather_kernel(const float* __restrict__ W_neg,      // [139][128]
                   const float* __restrict__ edge_attr,  // [E][6]
                   float* __restrict__ out, int E)
{
    const int lane = threadIdx.x & 31;
    const int warp = blockIdx.x * 8 + (threadIdx.x >> 5);
    const int beg  = warp * WIN;
    if (beg >= E) return;
    const int end = min(beg + WIN, E);

    unsigned long long wxy[6], wzw[6];
#pragma unroll
    for (int d = 0; d < 6; d++) {
        float4 w = __ldg((const float4*)(W_neg + (size_t)(133 + d) * 128) + lane);
        asm("mov.b64 %0, {%1, %2};" : "=l"(wxy[d]) : "f"(w.x), "f"(w.y));
        asm("mov.b64 %0, {%1, %2};" : "=l"(wzw[d]) : "f"(w.z), "f"(w.w));
    }

    float4 acc = make_float4(0.f, 0.f, 0.f, 0.f);
    int  cur   = -1;
    bool first = true;   // current run may extend into the previous window

    int j = beg;
    while (j < end) {
        int m = end - j; if (m > 4) m = 4;
        int4  rec[4];
        float4 v[4];
        float aa[4][6];
#pragma unroll
        for (int u = 0; u < 4; u++)
            if (u < m) rec[u] = __ldg(&g_sed[j + u]);
#pragma unroll
        for (int u = 0; u < 4; u++)
            if (u < m)
                v[u] = __ldg((const float4*)(g_yneg + (size_t)rec[u].x * 128) + lane);
#pragma unroll
        for (int u = 0; u < 4; u++)
            if (u < m) {
                const float2* ea = (const float2*)(edge_attr + (size_t)rec[u].y * 6);
                float2 p0 = __ldg(ea + 0);
                float2 p1 = __ldg(ea + 1);
                float2 p2 = __ldg(ea + 2);
                aa[u][0] = p0.x; aa[u][1] = p0.y; aa[u][2] = p1.x;
                aa[u][3] = p1.y; aa[u][4] = p2.x; aa[u][5] = p2.y;
            }
#pragma unroll
        for (int u = 0; u < 4; u++)
            if (u < m) {
                unsigned long long vxy, vzw;
                asm("mov.b64 %0, {%1, %2};" : "=l"(vxy) : "f"(v[u].x), "f"(v[u].y));
                asm("mov.b64 %0, {%1, %2};" : "=l"(vzw) : "f"(v[u].z), "f"(v[u].w));
#pragma unroll
                for (int d = 0; d < 6; d++) {
                    unsigned long long ad;
                    asm("mov.b64 %0, {%1, %1};" : "=l"(ad) : "f"(aa[u][d]));
                    asm("fma.rn.f32x2 %0, %1, %2, %0;" : "+l"(vxy)
                        : "l"(ad), "l"(wxy[d]));
                    asm("fma.rn.f32x2 %0, %1, %2, %0;" : "+l"(vzw)
                        : "l"(ad), "l"(wzw[d]));
                }
                asm("mov.b64 {%0, %1}, %2;" : "=f"(v[u].x), "=f"(v[u].y) : "l"(vxy));
                asm("mov.b64 {%0, %1}, %2;" : "=f"(v[u].z), "=f"(v[u].w) : "l"(vzw));
                v[u].x = eluf(v[u].x);
                v[u].y = eluf(v[u].y);
                v[u].z = eluf(v[u].z);
                v[u].w = eluf(v[u].w);
            }
        // segmented accumulation (warp-uniform control flow)
#pragma unroll
        for (int u = 0; u < 4; u++)
            if (u < m) {
                int d = rec[u].z;
                if (d != cur) {
                    if (cur >= 0) {
                        flush_acc(out, cur, lane, acc, first);
                        first = false;
                    }
                    cur = d;
                    acc = make_float4(0.f, 0.f, 0.f, 0.f);
                }
                acc.x += v[u].x; acc.y += v[u].y;
                acc.z += v[u].z; acc.w += v[u].w;
            }
        j += m;
    }
    if (cur >= 0) flush_acc(out, cur, lane, acc, true);  // last run: shared
}

// ---------------------------------------------------------------------------
extern "C" void kernel_launch(void* const* d_in, const int* in_sizes, int n_in,
                              void* d_out, int out_size)
{
    const float* x      = (const float*)d_in[0];
    const void*  ei     = d_in[1];
    const float* eattr  = (const float*)d_in[2];
    const float* gs     = (const float*)d_in[3];
    const float* W_neg  = (const float*)d_in[4];
    const float* b_neg  = (const float*)d_in[5];
    const float* W_root = (const float*)d_in[6];
    const float* b_root = (const float*)d_in[7];
    float* out = (float*)d_out;

    const int N  = in_sizes[0] / 128;   // 100000
    const int E  = in_sizes[2] / 6;     // 1600000
    const int NB = (N + 255) / 256;

    prep_kernel<<<128, 256>>>((const int*)ei, in_sizes[1], N);
    hist_kernel<<<(E + 255) / 256, 256>>>(ei, E);
    scan1_kernel<<<NB, 256>>>(N);
    scan2_kernel<<<1, 1024>>>(NB);
    scan3_kernel<<<NB, 256>>>(N, E);
    scatter_kernel<<<(E + 255) / 256, 256>>>(ei, E);

    node_gemm_kernel<<<(N + 63) / 64, 256>>>(x, gs, W_neg, b_neg,
                                             W_root, b_root, out, N);

    const int nwarps = (E + WIN - 1) / WIN;
    gather_kernel<<<(nwarps + 7) / 8, 256>>>(W_neg, eattr, out, E);
}

// round 8
// speedup vs baseline: 1.1689x; 1.1689x over previous
#include <cuda_runtime.h>
#include <math.h>

// NodeConv:
//   xs = [x | gs]  (133)
//   y_neg[n]  = xs[n] @ W_neg[0:133] + b_neg           (per NODE)
//   out[n]    = elu(xs[n] @ W_root + b_root)
//   out[dst] += sum_{e: dst(e)=dst} elu(y_neg[src(e)] + ea[e] @ W_neg[133:139])
//
// Counting-sort by dst -> per-node gather (R4 config, best measured).
// GEMM inner loop rebuilt on fma.rn.f32x2 (packed dual-FMA, sm_103a) with a
// transposed smem A-tile so A reads are 2 broadcast LDS.128 per k.

#define NMAX 100000
#define EMAX 1600000
#define NBMAX ((NMAX + 255) / 256)

__device__ float g_yneg[(size_t)NMAX * 128];
__device__ int2  g_se[EMAX];                  // sorted-by-dst: {src, eid}
__device__ int   g_count[NMAX];
__device__ int   g_offset[NMAX + 1];
__device__ int   g_cursor[NMAX];
__device__ int   g_blocksum[NBMAX];
__device__ int   g_blockoff[NBMAX];
__device__ int   g_is64;

// Branchless ELU: exact for v>=0 (__expf(0)==1), ~1e-7 abs err for v<0.
__device__ __forceinline__ float eluf(float v) {
    float neg = fminf(v, 0.0f);
    float pos = fmaxf(v, 0.0f);
    return pos + (__expf(neg) - 1.0f);
}

__device__ __forceinline__ int load_idx(const void* ei, int is64, size_t pos) {
    return is64 ? (int)__ldg((const long long*)ei + pos)
                : __ldg((const int*)ei + pos);
}

// ---------------------------------------------------------------------------
__global__ void prep_kernel(const int* __restrict__ ei32, int nwords, int N) {
    if (blockIdx.x == 0) {
        int nz = 0;
        for (int i = 1 + 2 * threadIdx.x; i < min(nwords, 4096); i += 2 * blockDim.x)
            nz |= (ei32[i] != 0);
        int any = __syncthreads_or(nz);
        if (threadIdx.x == 0) g_is64 = any ? 0 : 1;
    }
    for (int i = blockIdx.x * blockDim.x + threadIdx.x; i < N;
         i += gridDim.x * blockDim.x)
        g_count[i] = 0;
}

// ---------------------------------------------------------------------------
__global__ void hist_kernel(const void* __restrict__ ei, int E) {
    const int is64 = g_is64;
    int e = blockIdx.x * blockDim.x + threadIdx.x;
    if (e < E) atomicAdd(&g_count[load_idx(ei, is64, e)], 1);
}

// ---------------------------------------------------------------------------
__global__ __launch_bounds__(256)
void scan1_kernel(int N) {
    const int tid = threadIdx.x, lane = tid & 31, w = tid >> 5;
    __shared__ int wsum[8];
    int i = blockIdx.x * 256 + tid;
    int v = (i < N) ? g_count[i] : 0;
#pragma unroll
    for (int o = 16; o > 0; o >>= 1) v += __shfl_down_sync(0xffffffffu, v, o);
    if (lane == 0) wsum[w] = v;
    __syncthreads();
    if (tid == 0) {
        int s = 0;
#pragma unroll
        for (int k = 0; k < 8; k++) s += wsum[k];
        g_blocksum[blockIdx.x] = s;
    }
}

__global__ __launch_bounds__(1024)
void scan2_kernel(int NB) {
    const int tid = threadIdx.x, lane = tid & 31, w = tid >> 5;
    __shared__ int wtot[32];
    int c = (tid < NB) ? g_blocksum[tid] : 0;
    int v = c;
#pragma unroll
    for (int o = 1; o < 32; o <<= 1) {
        int t = __shfl_up_sync(0xffffffffu, v, o);
        if (lane >= o) v += t;
    }
    if (lane == 31) wtot[w] = v;
    __syncthreads();
    if (w == 0) {
        int s = wtot[lane];
#pragma unroll
        for (int o = 1; o < 32; o <<= 1) {
            int t = __shfl_up_sync(0xffffffffu, s, o);
            if (lane >= o) s += t;
        }
        wtot[lane] = s;
    }
    __syncthreads();
    int excl = ((w == 0) ? 0 : wtot[w - 1]) + v - c;
    if (tid < NB) g_blockoff[tid] = excl;
}

__global__ __launch_bounds__(256)
void scan3_kernel(int N, int E) {
    const int tid = threadIdx.x, lane = tid & 31, w = tid >> 5;
    __shared__ int wtot[8];
    int i = blockIdx.x * 256 + tid;
    int c = (i < N) ? g_count[i] : 0;
    int v = c;
#pragma unroll
    for (int o = 1; o < 32; o <<= 1) {
        int t = __shfl_up_sync(0xffffffffu, v, o);
        if (lane >= o) v += t;
    }
    if (lane == 31) wtot[w] = v;
    __syncthreads();
    if (w == 0 && lane < 8) {
        int s = wtot[lane];
#pragma unroll
        for (int o = 1; o < 8; o <<= 1) {
            int t = __shfl_up_sync(0x000000ffu, s, o);
            if (lane >= o) s += t;
        }
        wtot[lane] = s;
    }
    __syncthreads();
    int excl = g_blockoff[blockIdx.x] + ((w == 0) ? 0 : wtot[w - 1]) + v - c;
    if (i < N) {
        g_offset[i] = excl;
        g_cursor[i] = excl;
    }
    if (i == 0) g_offset[N] = E;
}

// ---------------------------------------------------------------------------
// Scatter: write {src, eid} into dst bucket. One 8B random store per edge.
// ---------------------------------------------------------------------------
__global__ __launch_bounds__(256)
void scatter_kernel(const void* __restrict__ ei, int E) {
    const int is64 = g_is64;
    int e = blockIdx.x * blockDim.x + threadIdx.x;
    if (e >= E) return;
    int dst = load_idx(ei, is64, e);
    int src = load_idx(ei, is64, (size_t)E + e);
    int pos = atomicAdd(&g_cursor[dst], 1);
    g_se[pos] = make_int2(src, e);
}

// ---------------------------------------------------------------------------
// K1: fused node GEMM on fma.rn.f32x2.
// Tile = 64 nodes x 256 outputs (128 y_neg | 128 root).
// As stored transposed [k][64] (pad 68) -> per-k A read = 2 broadcast LDS.128.
// Accumulators: 4 row-pairs x 8 cols packed f32x2 (row pairs come free from
// the float4 LDS; W columns are broadcast-duplicated).
// ---------------------------------------------------------------------------
__global__ __launch_bounds__(256, 2)
void node_gemm_kernel(const float* __restrict__ x,
                      const float* __restrict__ gs,
                      const float* __restrict__ W_neg,   // [139][128]
                      const float* __restrict__ b_neg,
                      const float* __restrict__ W_root,  // [133][128]
                      const float* __restrict__ b_root,
                      float* __restrict__ out,
                      int N)
{
    __shared__ __align__(16) float As[133][68];   // transposed, 16B-aligned rows
    const int tid = threadIdx.x;
    const int n0 = blockIdx.x * 64;

    for (int i = tid; i < 64 * 133; i += 256) {
        int m = i / 133;               // node within tile (coalesced global read)
        int k = i - m * 133;
        int n = n0 + m;
        float v = 0.0f;
        if (n < N) v = (k < 128) ? x[(size_t)n * 128 + k]
                                 : gs[(size_t)n * 5 + (k - 128)];
        As[k][m] = v;
    }
    __syncthreads();

    const int c = tid & 31;
    const int r = tid >> 5;
    const bool isRoot = (c >= 16);
    const float* Wsel = isRoot ? W_root : W_neg;
    const float* bsel = isRoot ? b_root : b_neg;
    const int cb = (isRoot ? (c - 16) : c) * 8;

    // acc[p][j]: rows (r*8+2p, r*8+2p+1) packed, column cb+j
    unsigned long long acc[4][8];
#pragma unroll
    for (int j = 0; j < 8; j++) {
        float bv = __ldg(bsel + cb + j);
        unsigned long long bb;
        asm("mov.b64 %0, {%1, %1};" : "=l"(bb) : "f"(bv));
#pragma unroll
        for (int p = 0; p < 4; p++) acc[p][j] = bb;
    }

#pragma unroll 2
    for (int k = 0; k < 133; k++) {
        float4 b0 = __ldg((const float4*)(Wsel + (size_t)k * 128 + cb));
        float4 b1 = __ldg((const float4*)(Wsel + (size_t)k * 128 + cb + 4));
        float4 a0 = *(const float4*)&As[k][r * 8];       // broadcast LDS.128
        float4 a1 = *(const float4*)&As[k][r * 8 + 4];

        unsigned long long ap[4], wd[8];
        asm("mov.b64 %0, {%1, %2};" : "=l"(ap[0]) : "f"(a0.x), "f"(a0.y));
        asm("mov.b64 %0, {%1, %2};" : "=l"(ap[1]) : "f"(a0.z), "f"(a0.w));
        asm("mov.b64 %0, {%1, %2};" : "=l"(ap[2]) : "f"(a1.x), "f"(a1.y));
        asm("mov.b64 %0, {%1, %2};" : "=l"(ap[3]) : "f"(a1.z), "f"(a1.w));
        asm("mov.b64 %0, {%1, %1};" : "=l"(wd[0]) : "f"(b0.x));
        asm("mov.b64 %0, {%1, %1};" : "=l"(wd[1]) : "f"(b0.y));
        asm("mov.b64 %0, {%1, %1};" : "=l"(wd[2]) : "f"(b0.z));
        asm("mov.b64 %0, {%1, %1};" : "=l"(wd[3]) : "f"(b0.w));
        asm("mov.b64 %0, {%1, %1};" : "=l"(wd[4]) : "f"(b1.x));
        asm("mov.b64 %0, {%1, %1};" : "=l"(wd[5]) : "f"(b1.y));
        asm("mov.b64 %0, {%1, %1};" : "=l"(wd[6]) : "f"(b1.z));
        asm("mov.b64 %0, {%1, %1};" : "=l"(wd[7]) : "f"(b1.w));

#pragma unroll
        for (int p = 0; p < 4; p++)
#pragma unroll
            for (int j = 0; j < 8; j++)
                asm("fma.rn.f32x2 %0, %1, %2, %0;"
                    : "+l"(acc[p][j]) : "l"(ap[p]), "l"(wd[j]));
    }

    // Epilogue: unpack row pairs, ELU for root half, store.
#pragma unroll
    for (int p = 0; p < 4; p++) {
        float lo[8], hi[8];
#pragma unroll
        for (int j = 0; j < 8; j++)
            asm("mov.b64 {%0, %1}, %2;" : "=f"(lo[j]), "=f"(hi[j]) : "l"(acc[p][j]));

        int n_lo = n0 + r * 8 + 2 * p;
        int n_hi = n_lo + 1;
        if (isRoot) {
            if (n_lo < N) {
                *((float4*)(out + (size_t)n_lo * 128 + cb)) =
                    make_float4(eluf(lo[0]), eluf(lo[1]), eluf(lo[2]), eluf(lo[3]));
                *((float4*)(out + (size_t)n_lo * 128 + cb + 4)) =
                    make_float4(eluf(lo[4]), eluf(lo[5]), eluf(lo[6]), eluf(lo[7]));
            }
            if (n_hi < N) {
                *((float4*)(out + (size_t)n_hi * 128 + cb)) =
                    make_float4(eluf(hi[0]), eluf(hi[1]), eluf(hi[2]), eluf(hi[3]));
                *((float4*)(out + (size_t)n_hi * 128 + cb + 4)) =
                    make_float4(eluf(hi[4]), eluf(hi[5]), eluf(hi[6]), eluf(hi[7]));
            }
        } else {
            if (n_lo < N) {
                *((float4*)(g_yneg + (size_t)n_lo * 128 + cb)) =
                    make_float4(lo[0], lo[1], lo[2], lo[3]);
                *((float4*)(g_yneg + (size_t)n_lo * 128 + cb + 4)) =
                    make_float4(lo[4], lo[5], lo[6], lo[7]);
            }
            if (n_hi < N) {
                *((float4*)(g_yneg + (size_t)n_hi * 128 + cb)) =
                    make_float4(hi[0], hi[1], hi[2], hi[3]);
                *((float4*)(g_yneg + (size_t)n_hi * 128 + cb + 4)) =
                    make_float4(hi[4], hi[5], hi[6], hi[7]);
            }
        }
    }
}

// ---------------------------------------------------------------------------
// Gather (R4 config, best measured): one warp per node, unroll x4.
// Per edge: int2 stream load, 3x float2 ea load, one dependent random
// 512B y_neg row load.
// ---------------------------------------------------------------------------
__global__ __launch_bounds__(256)
void gather_kernel(const float* __restrict__ W_neg,      // [139][128]
                   const float* __restrict__ edge_attr,  // [E][6]
                   float* __restrict__ out, int N)
{
    const int lane = threadIdx.x & 31;
    const int warp = blockIdx.x * (blockDim.x >> 5) + (threadIdx.x >> 5);
    if (warp >= N) return;
    const int n = warp;

    float4 w2[6];
#pragma unroll
    for (int d = 0; d < 6; d++)
        w2[d] = __ldg((const float4*)(W_neg + (size_t)(133 + d) * 128) + lane);

    const int beg = __ldg(&g_offset[n]);
    const int end = __ldg(&g_offset[n + 1]);
    float4 acc = make_float4(0.f, 0.f, 0.f, 0.f);

    int j = beg;
    for (; j + 4 <= end; j += 4) {
        int2   se[4];
        float4 v[4];
        float2 a01[4], a23[4], a45[4];
#pragma unroll
        for (int u = 0; u < 4; u++) se[u] = __ldg(&g_se[j + u]);
#pragma unroll
        for (int u = 0; u < 4; u++)
            v[u] = __ldg((const float4*)(g_yneg + (size_t)se[u].x * 128) + lane);
#pragma unroll
        for (int u = 0; u < 4; u++) {
            const float2* ea = (const float2*)(edge_attr + (size_t)se[u].y * 6);
            a01[u] = __ldg(ea + 0);
            a23[u] = __ldg(ea + 1);
            a45[u] = __ldg(ea + 2);
        }
#pragma unroll
        for (int u = 0; u < 4; u++) {
            v[u].x += a01[u].x * w2[0].x + a01[u].y * w2[1].x + a23[u].x * w2[2].x
                    + a23[u].y * w2[3].x + a45[u].x * w2[4].x + a45[u].y * w2[5].x;
            v[u].y += a01[u].x * w2[0].y + a01[u].y * w2[1].y + a23[u].x * w2[2].y
                    + a23[u].y * w2[3].y + a45[u].x * w2[4].y + a45[u].y * w2[5].y;
            v[u].z += a01[u].x * w2[0].z + a01[u].y * w2[1].z + a23[u].x * w2[2].z
                    + a23[u].y * w2[3].z + a45[u].x * w2[4].z + a45[u].y * w2[5].z;
            v[u].w += a01[u].x * w2[0].w + a01[u].y * w2[1].w + a23[u].x * w2[2].w
                    + a23[u].y * w2[3].w + a45[u].x * w2[4].w + a45[u].y * w2[5].w;
            acc.x += eluf(v[u].x);
            acc.y += eluf(v[u].y);
            acc.z += eluf(v[u].z);
            acc.w += eluf(v[u].w);
        }
    }
    for (; j < end; j++) {
        int2 se = __ldg(&g_se[j]);
        float4 v = __ldg((const float4*)(g_yneg + (size_t)se.x * 128) + lane);
        const float2* ea = (const float2*)(edge_attr + (size_t)se.y * 6);
        float2 a01 = __ldg(ea + 0);
        float2 a23 = __ldg(ea + 1);
        float2 a45 = __ldg(ea + 2);
        v.x += a01.x * w2[0].x + a01.y * w2[1].x + a23.x * w2[2].x
             + a23.y * w2[3].x + a45.x * w2[4].x + a45.y * w2[5].x;
        v.y += a01.x * w2[0].y + a01.y * w2[1].y + a23.x * w2[2].y
             + a23.y * w2[3].y + a45.x * w2[4].y + a45.y * w2[5].y;
        v.z += a01.x * w2[0].z + a01.y * w2[1].z + a23.x * w2[2].z
             + a23.y * w2[3].z + a45.x * w2[4].z + a45.y * w2[5].z;
        v.w += a01.x * w2[0].w + a01.y * w2[1].w + a23.x * w2[2].w
             + a23.y * w2[3].w + a45.x * w2[4].w + a45.y * w2[5].w;
        acc.x += eluf(v.x);
        acc.y += eluf(v.y);
        acc.z += eluf(v.z);
        acc.w += eluf(v.w);
    }

    float4* o = (float4*)(out + (size_t)n * 128) + lane;
    float4 cur = *o;
    cur.x += acc.x; cur.y += acc.y; cur.z += acc.z; cur.w += acc.w;
    *o = cur;
}

// ---------------------------------------------------------------------------
extern "C" void kernel_launch(void* const* d_in, const int* in_sizes, int n_in,
                              void* d_out, int out_size)
{
    const float* x      = (const float*)d_in[0];
    const void*  ei     = d_in[1];
    const float* eattr  = (const float*)d_in[2];
    const float* gs     = (const float*)d_in[3];
    const float* W_neg  = (const float*)d_in[4];
    const float* b_neg  = (const float*)d_in[5];
    const float* W_root = (const float*)d_in[6];
    const float* b_root = (const float*)d_in[7];
    float* out = (float*)d_out;

    const int N  = in_sizes[0] / 128;   // 100000
    const int E  = in_sizes[2] / 6;     // 1600000
    const int NB = (N + 255) / 256;

    prep_kernel<<<128, 256>>>((const int*)ei, in_sizes[1], N);
    hist_kernel<<<(E + 255) / 256, 256>>>(ei, E);
    scan1_kernel<<<NB, 256>>>(N);
    scan2_kernel<<<1, 1024>>>(NB);
    scan3_kernel<<<NB, 256>>>(N, E);
    scatter_kernel<<<(E + 255) / 256, 256>>>(ei, E);

    node_gemm_kernel<<<(N + 63) / 64, 256>>>(x, gs, W_neg, b_neg,
                                             W_root, b_root, out, N);

    gather_kernel<<<(N * 32 + 255) / 256, 256>>>(W_neg, eattr, out, N);
}

// round 9
// speedup vs baseline: 1.2561x; 1.0747x over previous
#include <cuda_runtime.h>
#include <cuda_fp16.h>
#include <math.h>

// NodeConv:
//   xs = [x | gs]  (133)
//   y_neg[n]  = xs[n] @ W_neg[0:133] + b_neg           (per NODE, stored fp16)
//   out[n]    = elu(xs[n] @ W_root + b_root)
//   out[dst] += sum_{e: dst(e)=dst} elu(y_neg[src(e)] + ea[e] @ W_neg[133:139])
//
// Counting-sort by dst -> per-node warp gather. y_neg stored in fp16 to halve
// the random-gather traffic and make the table L2-resident.

#define NMAX 100000
#define EMAX 1600000
#define NBMAX ((NMAX + 255) / 256)

__device__ __half g_yneg[(size_t)NMAX * 128];
__device__ int2   g_se[EMAX];                 // sorted-by-dst: {src, eid}
__device__ int    g_count[NMAX];
__device__ int    g_offset[NMAX + 1];
__device__ int    g_cursor[NMAX];
__device__ int    g_blocksum[NBMAX];
__device__ int    g_blockoff[NBMAX];
__device__ int    g_is64;

// Branchless ELU: exact for v>=0 (__expf(0)==1), ~1e-7 abs err for v<0.
__device__ __forceinline__ float eluf(float v) {
    float neg = fminf(v, 0.0f);
    float pos = fmaxf(v, 0.0f);
    return pos + (__expf(neg) - 1.0f);
}

__device__ __forceinline__ int load_idx(const void* ei, int is64, size_t pos) {
    return is64 ? (int)__ldg((const long long*)ei + pos)
                : __ldg((const int*)ei + pos);
}

// ---------------------------------------------------------------------------
__global__ void prep_kernel(const int* __restrict__ ei32, int nwords, int N) {
    if (blockIdx.x == 0) {
        int nz = 0;
        for (int i = 1 + 2 * threadIdx.x; i < min(nwords, 4096); i += 2 * blockDim.x)
            nz |= (ei32[i] != 0);
        int any = __syncthreads_or(nz);
        if (threadIdx.x == 0) g_is64 = any ? 0 : 1;
    }
    for (int i = blockIdx.x * blockDim.x + threadIdx.x; i < N;
         i += gridDim.x * blockDim.x)
        g_count[i] = 0;
}

// ---------------------------------------------------------------------------
__global__ void hist_kernel(const void* __restrict__ ei, int E) {
    const int is64 = g_is64;
    int e = blockIdx.x * blockDim.x + threadIdx.x;
    if (e < E) atomicAdd(&g_count[load_idx(ei, is64, e)], 1);
}

// ---------------------------------------------------------------------------
__global__ __launch_bounds__(256)
void scan1_kernel(int N) {
    const int tid = threadIdx.x, lane = tid & 31, w = tid >> 5;
    __shared__ int wsum[8];
    int i = blockIdx.x * 256 + tid;
    int v = (i < N) ? g_count[i] : 0;
#pragma unroll
    for (int o = 16; o > 0; o >>= 1) v += __shfl_down_sync(0xffffffffu, v, o);
    if (lane == 0) wsum[w] = v;
    __syncthreads();
    if (tid == 0) {
        int s = 0;
#pragma unroll
        for (int k = 0; k < 8; k++) s += wsum[k];
        g_blocksum[blockIdx.x] = s;
    }
}

__global__ __launch_bounds__(1024)
void scan2_kernel(int NB) {
    const int tid = threadIdx.x, lane = tid & 31, w = tid >> 5;
    __shared__ int wtot[32];
    int c = (tid < NB) ? g_blocksum[tid] : 0;
    int v = c;
#pragma unroll
    for (int o = 1; o < 32; o <<= 1) {
        int t = __shfl_up_sync(0xffffffffu, v, o);
        if (lane >= o) v += t;
    }
    if (lane == 31) wtot[w] = v;
    __syncthreads();
    if (w == 0) {
        int s = wtot[lane];
#pragma unroll
        for (int o = 1; o < 32; o <<= 1) {
            int t = __shfl_up_sync(0xffffffffu, s, o);
            if (lane >= o) s += t;
        }
        wtot[lane] = s;
    }
    __syncthreads();
    int excl = ((w == 0) ? 0 : wtot[w - 1]) + v - c;
    if (tid < NB) g_blockoff[tid] = excl;
}

__global__ __launch_bounds__(256)
void scan3_kernel(int N, int E) {
    const int tid = threadIdx.x, lane = tid & 31, w = tid >> 5;
    __shared__ int wtot[8];
    int i = blockIdx.x * 256 + tid;
    int c = (i < N) ? g_count[i] : 0;
    int v = c;
#pragma unroll
    for (int o = 1; o < 32; o <<= 1) {
        int t = __shfl_up_sync(0xffffffffu, v, o);
        if (lane >= o) v += t;
    }
    if (lane == 31) wtot[w] = v;
    __syncthreads();
    if (w == 0 && lane < 8) {
        int s = wtot[lane];
#pragma unroll
        for (int o = 1; o < 8; o <<= 1) {
            int t = __shfl_up_sync(0x000000ffu, s, o);
            if (lane >= o) s += t;
        }
        wtot[lane] = s;
    }
    __syncthreads();
    int excl = g_blockoff[blockIdx.x] + ((w == 0) ? 0 : wtot[w - 1]) + v - c;
    if (i < N) {
        g_offset[i] = excl;
        g_cursor[i] = excl;
    }
    if (i == 0) g_offset[N] = E;
}

// ---------------------------------------------------------------------------
// Scatter: write {src, eid} into dst bucket. One 8B random store per edge.
// ---------------------------------------------------------------------------
__global__ __launch_bounds__(256)
void scatter_kernel(const void* __restrict__ ei, int E) {
    const int is64 = g_is64;
    int e = blockIdx.x * blockDim.x + threadIdx.x;
    if (e >= E) return;
    int dst = load_idx(ei, is64, e);
    int src = load_idx(ei, is64, (size_t)E + e);
    int pos = atomicAdd(&g_cursor[dst], 1);
    g_se[pos] = make_int2(src, e);
}

// ---------------------------------------------------------------------------
// K1: fused node GEMM on fma.rn.f32x2.
// Tile = 64 nodes x 256 outputs (128 y_neg fp16 | 128 root fp32).
// ---------------------------------------------------------------------------
__global__ __launch_bounds__(256, 2)
void node_gemm_kernel(const float* __restrict__ x,
                      const float* __restrict__ gs,
                      const float* __restrict__ W_neg,   // [139][128]
                      const float* __restrict__ b_neg,
                      const float* __restrict__ W_root,  // [133][128]
                      const float* __restrict__ b_root,
                      float* __restrict__ out,
                      int N)
{
    __shared__ __align__(16) float As[133][68];   // transposed, 16B-aligned rows
    const int tid = threadIdx.x;
    const int n0 = blockIdx.x * 64;

    for (int i = tid; i < 64 * 133; i += 256) {
        int m = i / 133;
        int k = i - m * 133;
        int n = n0 + m;
        float v = 0.0f;
        if (n < N) v = (k < 128) ? x[(size_t)n * 128 + k]
                                 : gs[(size_t)n * 5 + (k - 128)];
        As[k][m] = v;
    }
    __syncthreads();

    const int c = tid & 31;
    const int r = tid >> 5;
    const bool isRoot = (c >= 16);
    const float* Wsel = isRoot ? W_root : W_neg;
    const float* bsel = isRoot ? b_root : b_neg;
    const int cb = (isRoot ? (c - 16) : c) * 8;

    unsigned long long acc[4][8];
#pragma unroll
    for (int j = 0; j < 8; j++) {
        float bv = __ldg(bsel + cb + j);
        unsigned long long bb;
        asm("mov.b64 %0, {%1, %1};" : "=l"(bb) : "f"(bv));
#pragma unroll
        for (int p = 0; p < 4; p++) acc[p][j] = bb;
    }

#pragma unroll 2
    for (int k = 0; k < 133; k++) {
        float4 b0 = __ldg((const float4*)(Wsel + (size_t)k * 128 + cb));
        float4 b1 = __ldg((const float4*)(Wsel + (size_t)k * 128 + cb + 4));
        float4 a0 = *(const float4*)&As[k][r * 8];
        float4 a1 = *(const float4*)&As[k][r * 8 + 4];

        unsigned long long ap[4], wd[8];
        asm("mov.b64 %0, {%1, %2};" : "=l"(ap[0]) : "f"(a0.x), "f"(a0.y));
        asm("mov.b64 %0, {%1, %2};" : "=l"(ap[1]) : "f"(a0.z), "f"(a0.w));
        asm("mov.b64 %0, {%1, %2};" : "=l"(ap[2]) : "f"(a1.x), "f"(a1.y));
        asm("mov.b64 %0, {%1, %2};" : "=l"(ap[3]) : "f"(a1.z), "f"(a1.w));
        asm("mov.b64 %0, {%1, %1};" : "=l"(wd[0]) : "f"(b0.x));
        asm("mov.b64 %0, {%1, %1};" : "=l"(wd[1]) : "f"(b0.y));
        asm("mov.b64 %0, {%1, %1};" : "=l"(wd[2]) : "f"(b0.z));
        asm("mov.b64 %0, {%1, %1};" : "=l"(wd[3]) : "f"(b0.w));
        asm("mov.b64 %0, {%1, %1};" : "=l"(wd[4]) : "f"(b1.x));
        asm("mov.b64 %0, {%1, %1};" : "=l"(wd[5]) : "f"(b1.y));
        asm("mov.b64 %0, {%1, %1};" : "=l"(wd[6]) : "f"(b1.z));
        asm("mov.b64 %0, {%1, %1};" : "=l"(wd[7]) : "f"(b1.w));

#pragma unroll
        for (int p = 0; p < 4; p++)
#pragma unroll
            for (int j = 0; j < 8; j++)
                asm("fma.rn.f32x2 %0, %1, %2, %0;"
                    : "+l"(acc[p][j]) : "l"(ap[p]), "l"(wd[j]));
    }

#pragma unroll
    for (int p = 0; p < 4; p++) {
        float lo[8], hi[8];
#pragma unroll
        for (int j = 0; j < 8; j++)
            asm("mov.b64 {%0, %1}, %2;" : "=f"(lo[j]), "=f"(hi[j]) : "l"(acc[p][j]));

        int n_lo = n0 + r * 8 + 2 * p;
        int n_hi = n_lo + 1;
        if (isRoot) {
            if (n_lo < N) {
                *((float4*)(out + (size_t)n_lo * 128 + cb)) =
                    make_float4(eluf(lo[0]), eluf(lo[1]), eluf(lo[2]), eluf(lo[3]));
                *((float4*)(out + (size_t)n_lo * 128 + cb + 4)) =
                    make_float4(eluf(lo[4]), eluf(lo[5]), eluf(lo[6]), eluf(lo[7]));
            }
            if (n_hi < N) {
                *((float4*)(out + (size_t)n_hi * 128 + cb)) =
                    make_float4(eluf(hi[0]), eluf(hi[1]), eluf(hi[2]), eluf(hi[3]));
                *((float4*)(out + (size_t)n_hi * 128 + cb + 4)) =
                    make_float4(eluf(hi[4]), eluf(hi[5]), eluf(hi[6]), eluf(hi[7]));
            }
        } else {
            // pack 8 fp32 -> 4 half2 -> one 16B store
            if (n_lo < N) {
                uint4 pk;
                __half2 h0 = __float22half2_rn(make_float2(lo[0], lo[1]));
                __half2 h1 = __float22half2_rn(make_float2(lo[2], lo[3]));
                __half2 h2 = __float22half2_rn(make_float2(lo[4], lo[5]));
                __half2 h3 = __float22half2_rn(make_float2(lo[6], lo[7]));
                pk.x = *(unsigned*)&h0; pk.y = *(unsigned*)&h1;
                pk.z = *(unsigned*)&h2; pk.w = *(unsigned*)&h3;
                *((uint4*)(g_yneg + (size_t)n_lo * 128 + cb)) = pk;
            }
            if (n_hi < N) {
                uint4 pk;
                __half2 h0 = __float22half2_rn(make_float2(hi[0], hi[1]));
                __half2 h1 = __float22half2_rn(make_float2(hi[2], hi[3]));
                __half2 h2 = __float22half2_rn(make_float2(hi[4], hi[5]));
                __half2 h3 = __float22half2_rn(make_float2(hi[6], hi[7]));
                pk.x = *(unsigned*)&h0; pk.y = *(unsigned*)&h1;
                pk.z = *(unsigned*)&h2; pk.w = *(unsigned*)&h3;
                *((uint4*)(g_yneg + (size_t)n_hi * 128 + cb)) = pk;
            }
        }
    }
}

// ---------------------------------------------------------------------------
// Gather: one warp per node, unroll x4. Per edge: int2 stream load, 3x float2
// ea load, one dependent random 256B fp16 y_neg row load (uint2 per lane).
// ---------------------------------------------------------------------------
__global__ __launch_bounds__(256)
void gather_kernel(const float* __restrict__ W_neg,      // [139][128]
                   const float* __restrict__ edge_attr,  // [E][6]
                   float* __restrict__ out, int N)
{
    const int lane = threadIdx.x & 31;
    const int warp = blockIdx.x * (blockDim.x >> 5) + (threadIdx.x >> 5);
    if (warp >= N) return;
    const int n = warp;

    float4 w2[6];
#pragma unroll
    for (int d = 0; d < 6; d++)
        w2[d] = __ldg((const float4*)(W_neg + (size_t)(133 + d) * 128) + lane);

    const int beg = __ldg(&g_offset[n]);
    const int end = __ldg(&g_offset[n + 1]);
    float4 acc = make_float4(0.f, 0.f, 0.f, 0.f);

    int j = beg;
    for (; j + 4 <= end; j += 4) {
        int2   se[4];
        uint2  hh[4];
        float2 a01[4], a23[4], a45[4];
#pragma unroll
        for (int u = 0; u < 4; u++) se[u] = __ldg(&g_se[j + u]);
#pragma unroll
        for (int u = 0; u < 4; u++)
            hh[u] = __ldg((const uint2*)(g_yneg + (size_t)se[u].x * 128) + lane);
#pragma unroll
        for (int u = 0; u < 4; u++) {
            const float2* ea = (const float2*)(edge_attr + (size_t)se[u].y * 6);
            a01[u] = __ldg(ea + 0);
            a23[u] = __ldg(ea + 1);
            a45[u] = __ldg(ea + 2);
        }
#pragma unroll
        for (int u = 0; u < 4; u++) {
            float2 f01 = __half22float2(*(__half2*)&hh[u].x);
            float2 f23 = __half22float2(*(__half2*)&hh[u].y);
            float4 v = make_float4(f01.x, f01.y, f23.x, f23.y);
            v.x += a01[u].x * w2[0].x + a01[u].y * w2[1].x + a23[u].x * w2[2].x
                 + a23[u].y * w2[3].x + a45[u].x * w2[4].x + a45[u].y * w2[5].x;
            v.y += a01[u].x * w2[0].y + a01[u].y * w2[1].y + a23[u].x * w2[2].y
                 + a23[u].y * w2[3].y + a45[u].x * w2[4].y + a45[u].y * w2[5].y;
            v.z += a01[u].x * w2[0].z + a01[u].y * w2[1].z + a23[u].x * w2[2].z
                 + a23[u].y * w2[3].z + a45[u].x * w2[4].z + a45[u].y * w2[5].z;
            v.w += a01[u].x * w2[0].w + a01[u].y * w2[1].w + a23[u].x * w2[2].w
                 + a23[u].y * w2[3].w + a45[u].x * w2[4].w + a45[u].y * w2[5].w;
            acc.x += eluf(v.x);
            acc.y += eluf(v.y);
            acc.z += eluf(v.z);
            acc.w += eluf(v.w);
        }
    }
    for (; j < end; j++) {
        int2 se = __ldg(&g_se[j]);
        uint2 hh = __ldg((const uint2*)(g_yneg + (size_t)se.x * 128) + lane);
        const float2* ea = (const float2*)(edge_attr + (size_t)se.y * 6);
        float2 a01 = __ldg(ea + 0);
        float2 a23 = __ldg(ea + 1);
        float2 a45 = __ldg(ea + 2);
        float2 f01 = __half22float2(*(__half2*)&hh.x);
        float2 f23 = __half22float2(*(__half2*)&hh.y);
        float4 v = make_float4(f01.x, f01.y, f23.x, f23.y);
        v.x += a01.x * w2[0].x + a01.y * w2[1].x + a23.x * w2[2].x
             + a23.y * w2[3].x + a45.x * w2[4].x + a45.y * w2[5].x;
        v.y += a01.x * w2[0].y + a01.y * w2[1].y + a23.x * w2[2].y
             + a23.y * w2[3].y + a45.x * w2[4].y + a45.y * w2[5].y;
        v.z += a01.x * w2[0].z + a01.y * w2[1].z + a23.x * w2[2].z
             + a23.y * w2[3].z + a45.x * w2[4].z + a45.y * w2[5].z;
        v.w += a01.x * w2[0].w + a01.y * w2[1].w + a23.x * w2[2].w
             + a23.y * w2[3].w + a45.x * w2[4].w + a45.y * w2[5].w;
        acc.x += eluf(v.x);
        acc.y += eluf(v.y);
        acc.z += eluf(v.z);
        acc.w += eluf(v.w);
    }

    float4* o = (float4*)(out + (size_t)n * 128) + lane;
    float4 cur = *o;
    cur.x += acc.x; cur.y += acc.y; cur.z += acc.z; cur.w += acc.w;
    *o = cur;
}

// ---------------------------------------------------------------------------
extern "C" void kernel_launch(void* const* d_in, const int* in_sizes, int n_in,
                              void* d_out, int out_size)
{
    const float* x      = (const float*)d_in[0];
    const void*  ei     = d_in[1];
    const float* eattr  = (const float*)d_in[2];
    const float* gs     = (const float*)d_in[3];
    const float* W_neg  = (const float*)d_in[4];
    const float* b_neg  = (const float*)d_in[5];
    const float* W_root = (const float*)d_in[6];
    const float* b_root = (const float*)d_in[7];
    float* out = (float*)d_out;

    const int N  = in_sizes[0] / 128;   // 100000
    const int E  = in_sizes[2] / 6;     // 1600000
    const int NB = (N + 255) / 256;

    prep_kernel<<<128, 256>>>((const int*)ei, in_sizes[1], N);
    hist_kernel<<<(E + 255) / 256, 256>>>(ei, E);
    scan1_kernel<<<NB, 256>>>(N);
    scan2_kernel<<<1, 1024>>>(NB);
    scan3_kernel<<<NB, 256>>>(N, E);
    scatter_kernel<<<(E + 255) / 256, 256>>>(ei, E);

    node_gemm_kernel<<<(N + 63) / 64, 256>>>(x, gs, W_neg, b_neg,
                                             W_root, b_root, out, N);

    gather_kernel<<<(N * 32 + 255) / 256, 256>>>(W_neg, eattr, out, N);
}